// round 1
// baseline (speedup 1.0000x reference)
#include <cuda_runtime.h>

#define BB 2
#define NN 40000
#define MM 40000
#define PP 128
#define KK 32
#define KC 4
#define FD 128
#define NQ2 (BB*PP*KK)   /* 8192 second-stage queries */
#define TILE 2048
#define FINF 3.402823466e38f

// ---------------- device scratch (no allocations allowed) ----------------
__device__ float4 g_noisyP4[BB*NN];   // xyz + |p|^2
__device__ float4 g_cleanP4[BB*MM];
__device__ float  g_f[NQ2*3];         // KNN-32 neighbor coords (the 2nd-stage queries)
__device__ float  g_q[BB*PP*3];       // sampled query points
__device__ float  g_c[BB*PP*3];       // noisy_feat @ Wc
__device__ float  g_partial[NQ2];     // per-query squared-diff sums

// ---------------- prep: pack points as float4 with |p|^2 ----------------
__global__ void prep_kernel(const float* __restrict__ noisy,
                            const float* __restrict__ clean) {
    int i = blockIdx.x * blockDim.x + threadIdx.x;
    if (i < BB*NN) {
        float x = noisy[3*i], y = noisy[3*i+1], z = noisy[3*i+2];
        g_noisyP4[i] = make_float4(x, y, z, x*x + y*y + z*z);
    }
    if (i < BB*MM) {
        float x = clean[3*i], y = clean[3*i+1], z = clean[3*i+2];
        g_cleanP4[i] = make_float4(x, y, z, x*x + y*y + z*z);
    }
}

// ---------------- gather q and c = (q@Wf)@Wc ----------------
__global__ void gather_kernel(const float* __restrict__ noisy,
                              const int*   __restrict__ sidx,
                              const float* __restrict__ Wf,
                              const float* __restrict__ Wc) {
    int t = blockIdx.x * blockDim.x + threadIdx.x;
    if (t >= BB*PP) return;
    int b = t >> 7, p = t & 127;
    int gi = b*NN + sidx[p];
    float qx = noisy[3*gi], qy = noisy[3*gi+1], qz = noisy[3*gi+2];
    float a0 = 0.f, a1 = 0.f, a2 = 0.f;
    for (int f = 0; f < FD; ++f) {
        float ft = qx*Wf[f] + qy*Wf[FD+f] + qz*Wf[2*FD+f];
        a0 += ft * Wc[3*f+0];
        a1 += ft * Wc[3*f+1];
        a2 += ft * Wc[3*f+2];
    }
    g_q[3*t] = qx; g_q[3*t+1] = qy; g_q[3*t+2] = qz;
    g_c[3*t] = a0; g_c[3*t+1] = a1; g_c[3*t+2] = a2;
}

// ---------------- KNN-32: one warp per query over noisy points ----------------
__global__ __launch_bounds__(256) void knn32_kernel() {
    __shared__ float4 tile[TILE];
    int tid = threadIdx.x, lane = tid & 31, warp = tid >> 5;
    int qid = blockIdx.x * 8 + warp;          // 0..255, 8 warps/block
    int b = qid >> 7;
    float qx = g_q[3*qid], qy = g_q[3*qid+1], qz = g_q[3*qid+2];
    float m2x = -2.f*qx, m2y = -2.f*qy, m2z = -2.f*qz;

    float ld[KK]; int li[KK];                 // local-mem per-lane top-32
    #pragma unroll
    for (int j = 0; j < KK; j++) { ld[j] = FINF; li[j] = 0; }
    float lmax = FINF; int lpos = 0;
    float tau = FINF;

    const float4* base = g_noisyP4 + b*NN;
    for (int t0 = 0; t0 < NN; t0 += TILE) {
        int n = min(TILE, NN - t0);
        __syncthreads();
        for (int j = tid; j < n; j += 256) tile[j] = base[t0 + j];
        __syncthreads();
        float bound = fminf(lmax, tau);
        for (int j = lane; j < n; j += 32) {
            float4 pt = tile[j];
            float s = fmaf(m2x, pt.x, fmaf(m2y, pt.y, fmaf(m2z, pt.z, pt.w)));
            if (s < bound) {
                ld[lpos] = s; li[lpos] = t0 + j;
                lmax = -FINF;
                #pragma unroll
                for (int u = 0; u < KK; u++)
                    if (ld[u] > lmax) { lmax = ld[u]; lpos = u; }
                bound = fminf(lmax, tau);
            }
        }
        if (t0 == 0) {
            // tau = (>=) 32nd-smallest of the first tile: safe upper bound on global 32nd
            float cp[KK];
            #pragma unroll
            for (int u = 0; u < KK; u++) cp[u] = ld[u];
            float last = FINF;
            for (int r = 0; r < KK; r++) {
                float mv = FINF; int mp = 0;
                #pragma unroll
                for (int u = 0; u < KK; u++)
                    if (cp[u] < mv) { mv = cp[u]; mp = u; }
                float v = mv;
                for (int off = 16; off; off >>= 1)
                    v = fminf(v, __shfl_xor_sync(0xffffffffu, v, off));
                if (mv == v) cp[mp] = FINF;   // pop (ties may over-pop: still an upper bound)
                last = v;
            }
            tau = last;
        }
    }

    // merge 32 lanes x top-32 -> global top-32, write neighbor coords (order irrelevant)
    for (int r = 0; r < KK; r++) {
        float mv = FINF; int mp = 0;
        #pragma unroll
        for (int u = 0; u < KK; u++)
            if (ld[u] < mv) { mv = ld[u]; mp = u; }
        float v = mv; int src = lane;
        for (int off = 16; off; off >>= 1) {
            float vo = __shfl_xor_sync(0xffffffffu, v, off);
            int   so = __shfl_xor_sync(0xffffffffu, src, off);
            if (vo < v || (vo == v && so < src)) { v = vo; src = so; }
        }
        int widx = __shfl_sync(0xffffffffu, li[mp], src);
        if (lane == src) ld[mp] = FINF;
        if (lane == 0) {
            float4 pp = base[widx];
            g_f[(qid*KK + r)*3 + 0] = pp.x;
            g_f[(qid*KK + r)*3 + 1] = pp.y;
            g_f[(qid*KK + r)*3 + 2] = pp.z;
        }
    }
}

// ---------------- KNN-4 + loss: 4 queries per warp over clean points ----------------
__global__ __launch_bounds__(256) void knn4_kernel(const float* __restrict__ Wx) {
    __shared__ float4 tile[TILE];
    int tid = threadIdx.x, lane = tid & 31, warp = tid >> 5;
    int qbase = (blockIdx.x * 8 + warp) * 4;   // 4 queries per warp
    int b = qbase >> 12;

    float m2x[4], m2y[4], m2z[4], fx[4], fy[4], fz[4];
    float d0[4], d1[4], d2[4], d3[4];
    int   i0[4], i1[4], i2[4], i3[4];
    float tau[4];
    #pragma unroll
    for (int s = 0; s < 4; s++) {
        int qi = qbase + s;
        fx[s] = g_f[3*qi]; fy[s] = g_f[3*qi+1]; fz[s] = g_f[3*qi+2];
        m2x[s] = -2.f*fx[s]; m2y[s] = -2.f*fy[s]; m2z[s] = -2.f*fz[s];
        d0[s] = d1[s] = d2[s] = d3[s] = FINF;
        i0[s] = i1[s] = i2[s] = i3[s] = 0;
        tau[s] = FINF;
    }

    const float4* base = g_cleanP4 + b*MM;
    for (int t0 = 0; t0 < MM; t0 += TILE) {
        int n = min(TILE, MM - t0);
        __syncthreads();
        for (int j = tid; j < n; j += 256) tile[j] = base[t0 + j];
        __syncthreads();
        for (int j = lane; j < n; j += 32) {
            float4 pt = tile[j];
            #pragma unroll
            for (int s = 0; s < 4; s++) {
                float t = fmaf(m2x[s], pt.x, fmaf(m2y[s], pt.y, fmaf(m2z[s], pt.z, pt.w)));
                if (t < fminf(d3[s], tau[s])) {      // rarely taken after tile 0
                    int id = t0 + j;
                    if (t < d2[s]) {
                        d3[s] = d2[s]; i3[s] = i2[s];
                        if (t < d1[s]) {
                            d2[s] = d1[s]; i2[s] = i1[s];
                            if (t < d0[s]) { d1[s] = d0[s]; i1[s] = i0[s]; d0[s] = t; i0[s] = id; }
                            else           { d1[s] = t; i1[s] = id; }
                        } else { d2[s] = t; i2[s] = id; }
                    } else { d3[s] = t; i3[s] = id; }
                }
            }
        }
        if (t0 == 0) {
            // tau[s] = (>=) 4th-smallest of the first tile
            #pragma unroll
            for (int s = 0; s < 4; s++) {
                float e0 = d0[s], e1 = d1[s], e2 = d2[s], e3 = d3[s];
                float last = FINF;
                for (int r = 0; r < KC; r++) {
                    float v = e0;
                    for (int off = 16; off; off >>= 1)
                        v = fminf(v, __shfl_xor_sync(0xffffffffu, v, off));
                    if (e0 == v) { e0 = e1; e1 = e2; e2 = e3; e3 = FINF; }
                    last = v;
                }
                tau[s] = last;
            }
        }
    }

    // merge + loss
    float w00 = Wx[0], w01 = Wx[1], w02 = Wx[2];
    float w10 = Wx[3], w11 = Wx[4], w12 = Wx[5];
    float w20 = Wx[6], w21 = Wx[7], w22 = Wx[8];

    #pragma unroll
    for (int s = 0; s < 4; s++) {
        float sx = 0.f, sy = 0.f, sz = 0.f;
        for (int r = 0; r < KC; r++) {
            float v = d0[s]; int src = lane;
            for (int off = 16; off; off >>= 1) {
                float vo = __shfl_xor_sync(0xffffffffu, v, off);
                int   so = __shfl_xor_sync(0xffffffffu, src, off);
                if (vo < v || (vo == v && so < src)) { v = vo; src = so; }
            }
            int widx = __shfl_sync(0xffffffffu, i0[s], src);
            if (lane == src) {
                d0[s] = d1[s]; i0[s] = i1[s];
                d1[s] = d2[s]; i1[s] = i2[s];
                d2[s] = d3[s]; i2[s] = i3[s];
                d3[s] = FINF;
            }
            float4 cp = base[widx];   // all lanes same address -> broadcast
            sx += cp.x; sy += cp.y; sz += cp.z;
        }
        if (lane == 0) {
            int qi = qbase + s;
            int bp = qi >> 5;         // b*128 + p
            float gx = 0.25f*sx - fx[s];
            float gy = 0.25f*sy - fy[s];
            float gz = 0.25f*sz - fz[s];
            float dx = fx[s] - g_q[3*bp];
            float dy = fy[s] - g_q[3*bp+1];
            float dz = fz[s] - g_q[3*bp+2];
            float ex = g_c[3*bp]   + dx*w00 + dy*w10 + dz*w20;
            float ey = g_c[3*bp+1] + dx*w01 + dy*w11 + dz*w21;
            float ez = g_c[3*bp+2] + dx*w02 + dy*w12 + dz*w22;
            float r0 = ex - gx, r1 = ey - gy, r2 = ez - gz;
            g_partial[qi] = fmaf(r0, r0, fmaf(r1, r1, r2*r2));
        }
    }
}

// ---------------- deterministic fixed-order reduction ----------------
__global__ void reduce_kernel(float* __restrict__ out) {
    __shared__ float sh[256];
    int tid = threadIdx.x;
    float s = 0.f;
    for (int i = tid; i < NQ2; i += 256) s += g_partial[i];
    sh[tid] = s;
    __syncthreads();
    for (int st = 128; st > 0; st >>= 1) {
        if (tid < st) sh[tid] += sh[tid + st];
        __syncthreads();
    }
    if (tid == 0) out[0] = sh[0] * (0.5f / (0.01f * 8192.0f));
}

// ---------------- launch ----------------
extern "C" void kernel_launch(void* const* d_in, const int* in_sizes, int n_in,
                              void* d_out, int out_size) {
    const float* noisy = (const float*)d_in[0];
    const float* clean = (const float*)d_in[1];
    const int*   sidx  = (const int*)  d_in[2];
    const float* Wf    = (const float*)d_in[3];
    const float* Wx    = (const float*)d_in[4];
    const float* Wc    = (const float*)d_in[5];
    float* out = (float*)d_out;

    prep_kernel  <<<(BB*NN + 255) / 256, 256>>>(noisy, clean);
    gather_kernel<<<1, 256>>>(noisy, sidx, Wf, Wc);
    knn32_kernel <<<32, 256>>>();
    knn4_kernel  <<<256, 256>>>(Wx);
    reduce_kernel<<<1, 256>>>(out);
}

// round 2
// speedup vs baseline: 1.7662x; 1.7662x over previous
#include <cuda_runtime.h>

#define BB 2
#define NN 40000
#define MM 40000
#define PP 128
#define KK 32
#define KC 4
#define FD 128
#define NQ2 (BB*PP*KK)   /* 8192 second-stage queries */
#define TILE 2048
#define CAP 4096
#define FINF 3.402823466e38f

// ---------------- device scratch (no allocations allowed) ----------------
__device__ float4 g_noisyP4[BB*NN];   // xyz + |p|^2
__device__ float4 g_cleanP4[BB*MM];
__device__ float  g_f[NQ2*3];         // KNN-32 neighbor coords (the 2nd-stage queries)
__device__ float  g_q[BB*PP*3];       // sampled query points
__device__ float  g_c[BB*PP*3];       // noisy_feat @ Wc
__device__ float  g_partial[NQ2];     // per-query squared-diff sums

// ---------------- prep: pack points as float4 with |p|^2 ----------------
__global__ void prep_kernel(const float* __restrict__ noisy,
                            const float* __restrict__ clean) {
    int i = blockIdx.x * blockDim.x + threadIdx.x;
    if (i < BB*NN) {
        float x = noisy[3*i], y = noisy[3*i+1], z = noisy[3*i+2];
        g_noisyP4[i] = make_float4(x, y, z, x*x + y*y + z*z);
    }
    if (i < BB*MM) {
        float x = clean[3*i], y = clean[3*i+1], z = clean[3*i+2];
        g_cleanP4[i] = make_float4(x, y, z, x*x + y*y + z*z);
    }
}

// ---------------- gather q and c = (q@Wf)@Wc ----------------
__global__ void gather_kernel(const float* __restrict__ noisy,
                              const int*   __restrict__ sidx,
                              const float* __restrict__ Wf,
                              const float* __restrict__ Wc) {
    int t = blockIdx.x * blockDim.x + threadIdx.x;
    if (t >= BB*PP) return;
    int b = t >> 7, p = t & 127;
    int gi = b*NN + sidx[p];
    float qx = noisy[3*gi], qy = noisy[3*gi+1], qz = noisy[3*gi+2];
    float a0 = 0.f, a1 = 0.f, a2 = 0.f;
    for (int f = 0; f < FD; ++f) {
        float ft = qx*Wf[f] + qy*Wf[FD+f] + qz*Wf[2*FD+f];
        a0 += ft * Wc[3*f+0];
        a1 += ft * Wc[3*f+1];
        a2 += ft * Wc[3*f+2];
    }
    g_q[3*t] = qx; g_q[3*t+1] = qy; g_q[3*t+2] = qz;
    g_c[3*t] = a0; g_c[3*t+1] = a1; g_c[3*t+2] = a2;
}

// ---------------- KNN-32: one CTA per query, tau-prefilter + compaction ----------------
// tau = 32nd smallest of the 256 per-thread minima (a subset order statistic,
// hence >= true 32nd-NN distance). Every true top-32 point has s <= tau, so the
// compacted buffer (expected ~tens of entries) always contains the answer.
__global__ __launch_bounds__(256) void knn32_kernel() {
    __shared__ float sh_min[256];
    __shared__ float buf_d[CAP];
    __shared__ int   buf_i[CAP];
    __shared__ int   sh_cnt;
    __shared__ float sh_tau;
    int tid = threadIdx.x, lane = tid & 31, warp = tid >> 5;
    int qid = blockIdx.x;                 // 0..255
    int b = qid >> 7;
    float qx = g_q[3*qid], qy = g_q[3*qid+1], qz = g_q[3*qid+2];
    float m2x = -2.f*qx, m2y = -2.f*qy, m2z = -2.f*qz;
    const float4* base = g_noisyP4 + b*NN;

    // Phase A: per-thread min over strided slice
    float mn = FINF;
    for (int i = tid; i < NN; i += 256) {
        float4 p = base[i];
        float s = fmaf(m2x, p.x, fmaf(m2y, p.y, fmaf(m2z, p.z, p.w)));
        mn = fminf(mn, s);
    }
    sh_min[tid] = mn;
    if (tid == 0) sh_cnt = 0;
    __syncthreads();

    // warp 0: extract 32nd smallest of the 256 thread-mins -> tau
    if (warp == 0) {
        float e[8];
        #pragma unroll
        for (int u = 0; u < 8; u++) e[u] = sh_min[lane + 32*u];
        float tau = FINF;
        for (int r = 0; r < KK; r++) {
            float mv = e[0]; int mp = 0;
            #pragma unroll
            for (int u = 1; u < 8; u++)
                if (e[u] < mv) { mv = e[u]; mp = u; }
            float v = mv; int src = lane;
            for (int off = 16; off; off >>= 1) {
                float vo = __shfl_xor_sync(0xffffffffu, v, off);
                int   so = __shfl_xor_sync(0xffffffffu, src, off);
                if (vo < v || (vo == v && so < src)) { v = vo; src = so; }
            }
            if (lane == src) {
                #pragma unroll
                for (int u = 0; u < 8; u++) if (u == mp) e[u] = FINF;
            }
            tau = v;
        }
        if (lane == 0) sh_tau = tau;
    }
    __syncthreads();
    float tau = sh_tau;

    // Phase B: compact survivors
    for (int i = tid; i < NN; i += 256) {
        float4 p = base[i];
        float s = fmaf(m2x, p.x, fmaf(m2y, p.y, fmaf(m2z, p.z, p.w)));
        if (s <= tau) {
            int pos = atomicAdd(&sh_cnt, 1);
            if (pos < CAP) { buf_d[pos] = s; buf_i[pos] = i; }
        }
    }
    __syncthreads();
    int cnt = min(sh_cnt, CAP);

    // warp 0: extract top-32 from buffer, write neighbor coords (order irrelevant)
    if (warp == 0) {
        for (int r = 0; r < KK; r++) {
            float mv = FINF; int mi = -1;
            for (int j = lane; j < cnt; j += 32) {
                float dv = buf_d[j];
                if (dv < mv) { mv = dv; mi = j; }
            }
            float v = mv; int src = lane;
            for (int off = 16; off; off >>= 1) {
                float vo = __shfl_xor_sync(0xffffffffu, v, off);
                int   so = __shfl_xor_sync(0xffffffffu, src, off);
                if (vo < v || (vo == v && so < src)) { v = vo; src = so; }
            }
            int slot = __shfl_sync(0xffffffffu, mi, src);
            if (lane == 0) {
                float4 pp = base[buf_i[slot]];
                g_f[(qid*KK + r)*3 + 0] = pp.x;
                g_f[(qid*KK + r)*3 + 1] = pp.y;
                g_f[(qid*KK + r)*3 + 2] = pp.z;
            }
            if (lane == src) buf_d[slot] = FINF;
            __syncwarp();
        }
    }
}

// ---------------- KNN-4 + loss: 4 queries per warp over clean points ----------------
__global__ __launch_bounds__(256) void knn4_kernel(const float* __restrict__ Wx) {
    __shared__ float4 tile[TILE];
    int tid = threadIdx.x, lane = tid & 31, warp = tid >> 5;
    int qbase = (blockIdx.x * 8 + warp) * 4;   // 4 queries per warp
    int b = qbase >> 12;

    float m2x[4], m2y[4], m2z[4], fx[4], fy[4], fz[4];
    float d0[4], d1[4], d2[4], d3[4], bnd[4], tau[4];
    int   i0[4], i1[4], i2[4], i3[4];
    #pragma unroll
    for (int s = 0; s < 4; s++) {
        int qi = qbase + s;
        fx[s] = g_f[3*qi]; fy[s] = g_f[3*qi+1]; fz[s] = g_f[3*qi+2];
        m2x[s] = -2.f*fx[s]; m2y[s] = -2.f*fy[s]; m2z[s] = -2.f*fz[s];
        d0[s] = d1[s] = d2[s] = d3[s] = FINF;
        i0[s] = i1[s] = i2[s] = i3[s] = 0;
        bnd[s] = FINF; tau[s] = FINF;
    }

    const float4* base = g_cleanP4 + b*MM;
    for (int t0 = 0; t0 < MM; t0 += TILE) {
        int n = min(TILE, MM - t0);       // 2048 or 1088, both multiples of 64
        __syncthreads();
        for (int j = tid; j < n; j += 256) tile[j] = base[t0 + j];
        __syncthreads();
        for (int j = lane; j < n; j += 64) {
            float4 pa = tile[j];
            float4 pb = tile[j + 32];
            #pragma unroll
            for (int s = 0; s < 4; s++) {
                float ta = fmaf(m2x[s], pa.x, fmaf(m2y[s], pa.y, fmaf(m2z[s], pa.z, pa.w)));
                if (ta < bnd[s]) {                       // rarely taken after tile 0
                    int id = t0 + j;
                    if (ta < d2[s]) {
                        d3[s] = d2[s]; i3[s] = i2[s];
                        if (ta < d1[s]) {
                            d2[s] = d1[s]; i2[s] = i1[s];
                            if (ta < d0[s]) { d1[s] = d0[s]; i1[s] = i0[s]; d0[s] = ta; i0[s] = id; }
                            else            { d1[s] = ta; i1[s] = id; }
                        } else { d2[s] = ta; i2[s] = id; }
                    } else { d3[s] = ta; i3[s] = id; }
                    bnd[s] = fminf(d3[s], tau[s]);
                }
                float tb = fmaf(m2x[s], pb.x, fmaf(m2y[s], pb.y, fmaf(m2z[s], pb.z, pb.w)));
                if (tb < bnd[s]) {
                    int id = t0 + j + 32;
                    if (tb < d2[s]) {
                        d3[s] = d2[s]; i3[s] = i2[s];
                        if (tb < d1[s]) {
                            d2[s] = d1[s]; i2[s] = i1[s];
                            if (tb < d0[s]) { d1[s] = d0[s]; i1[s] = i0[s]; d0[s] = tb; i0[s] = id; }
                            else            { d1[s] = tb; i1[s] = id; }
                        } else { d2[s] = tb; i2[s] = id; }
                    } else { d3[s] = tb; i3[s] = id; }
                    bnd[s] = fminf(d3[s], tau[s]);
                }
            }
        }
        if (t0 == 0) {
            // tau[s] = (>=) 4th-smallest of the first tile (subset order statistic)
            #pragma unroll
            for (int s = 0; s < 4; s++) {
                float e0 = d0[s], e1 = d1[s], e2 = d2[s], e3 = d3[s];
                float last = FINF;
                for (int r = 0; r < KC; r++) {
                    float v = e0;
                    for (int off = 16; off; off >>= 1)
                        v = fminf(v, __shfl_xor_sync(0xffffffffu, v, off));
                    if (e0 == v) { e0 = e1; e1 = e2; e2 = e3; e3 = FINF; }
                    last = v;
                }
                tau[s] = last;
                bnd[s] = fminf(d3[s], tau[s]);
            }
        }
    }

    // merge + loss
    float w00 = Wx[0], w01 = Wx[1], w02 = Wx[2];
    float w10 = Wx[3], w11 = Wx[4], w12 = Wx[5];
    float w20 = Wx[6], w21 = Wx[7], w22 = Wx[8];

    #pragma unroll
    for (int s = 0; s < 4; s++) {
        float sx = 0.f, sy = 0.f, sz = 0.f;
        for (int r = 0; r < KC; r++) {
            float v = d0[s]; int src = lane;
            for (int off = 16; off; off >>= 1) {
                float vo = __shfl_xor_sync(0xffffffffu, v, off);
                int   so = __shfl_xor_sync(0xffffffffu, src, off);
                if (vo < v || (vo == v && so < src)) { v = vo; src = so; }
            }
            int widx = __shfl_sync(0xffffffffu, i0[s], src);
            if (lane == src) {
                d0[s] = d1[s]; i0[s] = i1[s];
                d1[s] = d2[s]; i1[s] = i2[s];
                d2[s] = d3[s]; i2[s] = i3[s];
                d3[s] = FINF;
            }
            float4 cp = base[widx];   // all lanes same address -> broadcast
            sx += cp.x; sy += cp.y; sz += cp.z;
        }
        if (lane == 0) {
            int qi = qbase + s;
            int bp = qi >> 5;         // b*128 + p
            float gx = 0.25f*sx - fx[s];
            float gy = 0.25f*sy - fy[s];
            float gz = 0.25f*sz - fz[s];
            float dx = fx[s] - g_q[3*bp];
            float dy = fy[s] - g_q[3*bp+1];
            float dz = fz[s] - g_q[3*bp+2];
            float ex = g_c[3*bp]   + dx*w00 + dy*w10 + dz*w20;
            float ey = g_c[3*bp+1] + dx*w01 + dy*w11 + dz*w21;
            float ez = g_c[3*bp+2] + dx*w02 + dy*w12 + dz*w22;
            float r0 = ex - gx, r1 = ey - gy, r2 = ez - gz;
            g_partial[qi] = fmaf(r0, r0, fmaf(r1, r1, r2*r2));
        }
    }
}

// ---------------- deterministic fixed-order reduction ----------------
__global__ void reduce_kernel(float* __restrict__ out) {
    __shared__ float sh[256];
    int tid = threadIdx.x;
    float s = 0.f;
    for (int i = tid; i < NQ2; i += 256) s += g_partial[i];
    sh[tid] = s;
    __syncthreads();
    for (int st = 128; st > 0; st >>= 1) {
        if (tid < st) sh[tid] += sh[tid + st];
        __syncthreads();
    }
    if (tid == 0) out[0] = sh[0] * (0.5f / (0.01f * 8192.0f));
}

// ---------------- launch ----------------
extern "C" void kernel_launch(void* const* d_in, const int* in_sizes, int n_in,
                              void* d_out, int out_size) {
    const float* noisy = (const float*)d_in[0];
    const float* clean = (const float*)d_in[1];
    const int*   sidx  = (const int*)  d_in[2];
    const float* Wf    = (const float*)d_in[3];
    const float* Wx    = (const float*)d_in[4];
    const float* Wc    = (const float*)d_in[5];
    float* out = (float*)d_out;

    prep_kernel  <<<(BB*NN + 255) / 256, 256>>>(noisy, clean);
    gather_kernel<<<1, 256>>>(noisy, sidx, Wf, Wc);
    knn32_kernel <<<BB*PP, 256>>>();
    knn4_kernel  <<<256, 256>>>(Wx);
    reduce_kernel<<<1, 256>>>(out);
}